// round 7
// baseline (speedup 1.0000x reference)
#include <cuda_runtime.h>

// Problem shape (from reference): B=16, S=64 -> h=w=64, hw=4096.
// d_in[0] = corr_m  [B, 4096, 4096] f32
// d_in[1] = gt_flow [B, 2, 64, 64]  f32
// d_in[2] = vis_mask[B, 1, 64, 64]  f32
// d_out   = scalar f32 (mean of |filtered_corr*vis - weights*vis|)

#define HW 4096      // h*w
#define W_DIM 64
#define THREADS 256
#define MAX_BLOCKS 1024

__device__ float g_partials[MAX_BLOCKS];

__global__ __launch_bounds__(THREADS)
void smpl_partial_kernel(const float* __restrict__ corr,
                         const float* __restrict__ gt,
                         const float* __restrict__ vis)
{
    const int t = blockIdx.x * THREADS + threadIdx.x;   // one thread per (b, pixel)
    const int b = t >> 12;          // / 4096
    const int p = t & (HW - 1);     // % 4096

    // gt_flow[b, 0, p] and gt_flow[b, 1, p]
    const float gfx = gt[(size_t)b * 2 * HW + p];
    const float gfy = gt[(size_t)b * 2 * HW + HW + p];
    const float v   = vis[(size_t)b * HW + p];

    // gx scaled by (w-1)/2 = 31.5, gy by (h-1)/2 = 31.5
    const float gx = (gfx + 1.0f) * 31.5f;
    const float gy = (gfy + 1.0f) * 31.5f;
    const float fx = floorf(gx);
    const float fy = floorf(gy);

    const float ax = fx + 1.0f - gx;   // (1 - frac_x)
    const float bx = gx - fx;          // frac_x
    const float ay = fy + 1.0f - gy;   // (1 - frac_y)
    const float by = gy - fy;          // frac_y

    // weights ordered per offsets (ox,oy) = (0,0),(0,1),(1,0),(1,1)
    const float w0 = ay * ax;
    const float w1 = ay * bx;
    const float w2 = by * ax;
    const float w3 = by * bx;

    // idx_i = clip(fy + ox_i, 0, 63)*64 + clip(fx + oy_i, 0, 63)
    // (note: reference pairs fy with offset_x in the row slot — replicated verbatim)
    const float r0 = fminf(fmaxf(fy,        0.0f), 63.0f);
    const float r1 = fminf(fmaxf(fy + 1.0f, 0.0f), 63.0f);
    const float c0 = fminf(fmaxf(fx,        0.0f), 63.0f);
    const float c1 = fminf(fmaxf(fx + 1.0f, 0.0f), 63.0f);

    const int i0 = (int)r0 * W_DIM + (int)c0;  // (ox,oy)=(0,0)
    const int i1 = (int)r0 * W_DIM + (int)c1;  // (0,1)
    const int i2 = (int)r1 * W_DIM + (int)c0;  // (1,0)
    const int i3 = (int)r1 * W_DIM + (int)c1;  // (1,1)

    // corr_m[b, p, idx] : row base = (b*4096 + p) * 4096 = t * 4096
    const float* __restrict__ row = corr + (size_t)t * HW;
    const float g0 = __ldg(row + i0);
    const float g1 = __ldg(row + i1);
    const float g2 = __ldg(row + i2);
    const float g3 = __ldg(row + i3);

    float s = fabsf(g0 * v - w0 * v)
            + fabsf(g1 * v - w1 * v)
            + fabsf(g2 * v - w2 * v)
            + fabsf(g3 * v - w3 * v);

    // deterministic block tree reduction
    __shared__ float red[THREADS];
    red[threadIdx.x] = s;
    __syncthreads();
    #pragma unroll
    for (int off = THREADS / 2; off > 0; off >>= 1) {
        if (threadIdx.x < off) red[threadIdx.x] += red[threadIdx.x + off];
        __syncthreads();
    }
    if (threadIdx.x == 0) g_partials[blockIdx.x] = red[0];
}

__global__ __launch_bounds__(THREADS)
void smpl_final_kernel(float* __restrict__ out, int n_blocks, float inv_count)
{
    __shared__ float red[THREADS];
    float s = 0.0f;
    for (int i = threadIdx.x; i < n_blocks; i += THREADS)
        s += g_partials[i];
    red[threadIdx.x] = s;
    __syncthreads();
    #pragma unroll
    for (int off = THREADS / 2; off > 0; off >>= 1) {
        if (threadIdx.x < off) red[threadIdx.x] += red[threadIdx.x + off];
        __syncthreads();
    }
    if (threadIdx.x == 0) out[0] = red[0] * inv_count;
}

extern "C" void kernel_launch(void* const* d_in, const int* in_sizes, int n_in,
                              void* d_out, int out_size)
{
    const float* corr = (const float*)d_in[0];
    const float* gt   = (const float*)d_in[1];
    const float* vis  = (const float*)d_in[2];
    float* out = (float*)d_out;

    const int B = in_sizes[2] / HW;            // vis_mask has B*1*64*64 elements
    const int total = B * HW;                  // one thread per (b, pixel)
    const int n_blocks = total / THREADS;      // 256 for B=16

    const float inv_count = 1.0f / (float)(B * 4 * HW);

    smpl_partial_kernel<<<n_blocks, THREADS>>>(corr, gt, vis);
    smpl_final_kernel<<<1, THREADS>>>(out, n_blocks, inv_count);
}

// round 9
// speedup vs baseline: 1.0257x; 1.0257x over previous
#include <cuda_runtime.h>

// Problem shape (from reference): B=16, S=64 -> h=w=64, hw=4096.
// d_in[0] = corr_m  [B, 4096, 4096] f32
// d_in[1] = gt_flow [B, 2, 64, 64]  f32
// d_in[2] = vis_mask[B, 1, 64, 64]  f32
// d_out   = scalar f32 (mean of |filtered_corr*vis - weights*vis|)

#define HW 4096      // h*w
#define W_DIM 64
#define THREADS 512
#define NBLOCKS 128  // B*HW / THREADS = 65536/512

__device__ float        g_partials[NBLOCKS];
__device__ unsigned int g_count;   // zero-initialized; last block resets it

__global__ __launch_bounds__(THREADS)
void smpl_fused_kernel(const float* __restrict__ corr,
                       const float* __restrict__ gt,
                       const float* __restrict__ vis,
                       float* __restrict__ out,
                       float inv_count)
{
    const int t = blockIdx.x * THREADS + threadIdx.x;   // one thread per (b, pixel)
    const int b = t >> 12;          // / 4096
    const int p = t & (HW - 1);     // % 4096

    // gt_flow[b, 0, p] and gt_flow[b, 1, p]
    const float gfx = __ldg(gt + (size_t)b * 2 * HW + p);
    const float gfy = __ldg(gt + (size_t)b * 2 * HW + HW + p);
    const float v   = __ldg(vis + (size_t)b * HW + p);

    // gx scaled by (w-1)/2 = 31.5, gy by (h-1)/2 = 31.5
    const float gx = (gfx + 1.0f) * 31.5f;
    const float gy = (gfy + 1.0f) * 31.5f;
    const float fx = floorf(gx);
    const float fy = floorf(gy);

    const float ax = fx + 1.0f - gx;   // (1 - frac_x)
    const float bx = gx - fx;          // frac_x
    const float ay = fy + 1.0f - gy;   // (1 - frac_y)
    const float by = gy - fy;          // frac_y

    // weights ordered per offsets (ox,oy) = (0,0),(0,1),(1,0),(1,1)
    const float w0 = ay * ax;
    const float w1 = ay * bx;
    const float w2 = by * ax;
    const float w3 = by * bx;

    // idx_i = clip(fy + ox_i, 0, 63)*64 + clip(fx + oy_i, 0, 63)
    // (reference pairs fy with offset_x in the row slot — replicated verbatim)
    const float r0 = fminf(fmaxf(fy,        0.0f), 63.0f);
    const float r1 = fminf(fmaxf(fy + 1.0f, 0.0f), 63.0f);
    const float c0 = fminf(fmaxf(fx,        0.0f), 63.0f);
    const float c1 = fminf(fmaxf(fx + 1.0f, 0.0f), 63.0f);

    const int i0 = (int)r0 * W_DIM + (int)c0;  // (ox,oy)=(0,0)
    const int i1 = (int)r0 * W_DIM + (int)c1;  // (0,1)
    const int i2 = (int)r1 * W_DIM + (int)c0;  // (1,0)
    const int i3 = (int)r1 * W_DIM + (int)c1;  // (1,1)

    // corr_m[b, p, idx] : row base = (b*4096 + p) * 4096 = t * 4096
    const float* __restrict__ row = corr + (size_t)t * HW;
    const float g0 = __ldg(row + i0);
    const float g1 = __ldg(row + i1);
    const float g2 = __ldg(row + i2);
    const float g3 = __ldg(row + i3);

    float s = fabsf(g0 * v - w0 * v)
            + fabsf(g1 * v - w1 * v)
            + fabsf(g2 * v - w2 * v)
            + fabsf(g3 * v - w3 * v);

    // deterministic block tree reduction
    __shared__ float red[THREADS];
    red[threadIdx.x] = s;
    __syncthreads();
    #pragma unroll
    for (int off = THREADS / 2; off > 0; off >>= 1) {
        if (threadIdx.x < off) red[threadIdx.x] += red[threadIdx.x + off];
        __syncthreads();
    }

    // decoupled last-block finalization (deterministic: fixed summation order)
    __shared__ bool is_last;
    if (threadIdx.x == 0) {
        g_partials[blockIdx.x] = red[0];
        __threadfence();
        unsigned int prev = atomicAdd(&g_count, 1u);
        is_last = (prev == (unsigned int)(gridDim.x - 1));
    }
    __syncthreads();

    if (is_last) {
        // 128 partials, tree-reduced in fixed order by the last block
        float ps = (threadIdx.x < NBLOCKS) ? g_partials[threadIdx.x] : 0.0f;
        red[threadIdx.x] = ps;
        __syncthreads();
        #pragma unroll
        for (int off = THREADS / 2; off > 0; off >>= 1) {
            if (threadIdx.x < off) red[threadIdx.x] += red[threadIdx.x + off];
            __syncthreads();
        }
        if (threadIdx.x == 0) {
            out[0] = red[0] * inv_count;
            g_count = 0;            // reset for next graph replay
            __threadfence();
        }
    }
}

extern "C" void kernel_launch(void* const* d_in, const int* in_sizes, int n_in,
                              void* d_out, int out_size)
{
    const float* corr = (const float*)d_in[0];
    const float* gt   = (const float*)d_in[1];
    const float* vis  = (const float*)d_in[2];
    float* out = (float*)d_out;

    const int B = in_sizes[2] / HW;            // vis_mask has B*1*64*64 elements
    const int total = B * HW;
    const int n_blocks = total / THREADS;      // 128 for B=16

    const float inv_count = 1.0f / (float)(B * 4 * HW);

    smpl_fused_kernel<<<n_blocks, THREADS>>>(corr, gt, vis, out, inv_count);
}